// round 2
// baseline (speedup 1.0000x reference)
#include <cuda_runtime.h>

// Warp3d: out[n, h, w, d] = trilinear_sample(x[n], grid + flow[n]),
// zeros padding, per the JAX reference.
// Shapes: x (3, H, W, D), w (3, 3, H, W, D), out (3, H, W, D), fp32.

constexpr int H = 160, W = 192, D = 160;
constexpr int WD  = W * D;          // 30720
constexpr int HWD = H * WD;         // 4915200
constexpr int NMAPS = 3;
constexpr int VEC = 4;              // D % 4 == 0
constexpr long TOTAL_V = (long)NMAPS * HWD / VEC;

__device__ __forceinline__ float corner_load(const float* __restrict__ vol,
                                             int ix, int iy, int iz) {
    bool valid = ((unsigned)ix < (unsigned)H) &
                 ((unsigned)iy < (unsigned)W) &
                 ((unsigned)iz < (unsigned)D);
    int cx = min(max(ix, 0), H - 1);
    int cy = min(max(iy, 0), W - 1);
    int cz = min(max(iz, 0), D - 1);
    float v = __ldg(vol + (long)cx * WD + cy * D + cz);
    return valid ? v : 0.0f;
}

__device__ __forceinline__ float trilerp(const float* __restrict__ vol,
                                         float cx, float cy, float cz) {
    float x0f = floorf(cx), y0f = floorf(cy), z0f = floorf(cz);
    float fx = cx - x0f, fy = cy - y0f, fz = cz - z0f;
    int x0 = (int)x0f, y0 = (int)y0f, z0 = (int)z0f;

    float gx0 = 1.0f - fx, gy0 = 1.0f - fy, gz0 = 1.0f - fz;

    float v000, v100, v010, v001, v110, v101, v011, v111;

    // Fast path: whole 2x2x2 cube strictly in-bounds (>95% of voxels for
    // N(0,1) flow on a 160^3 grid). One check, 8 offset loads off one base.
    if (((unsigned)x0 < (unsigned)(H - 1)) &
        ((unsigned)y0 < (unsigned)(W - 1)) &
        ((unsigned)z0 < (unsigned)(D - 1))) {
        const float* p = vol + (long)x0 * WD + y0 * D + z0;
        v000 = __ldg(p);
        v001 = __ldg(p + 1);
        v010 = __ldg(p + D);
        v011 = __ldg(p + D + 1);
        v100 = __ldg(p + WD);
        v101 = __ldg(p + WD + 1);
        v110 = __ldg(p + WD + D);
        v111 = __ldg(p + WD + D + 1);
    } else {
        int x1 = x0 + 1, y1 = y0 + 1, z1 = z0 + 1;
        v000 = corner_load(vol, x0, y0, z0);
        v100 = corner_load(vol, x1, y0, z0);
        v010 = corner_load(vol, x0, y1, z0);
        v001 = corner_load(vol, x0, y0, z1);
        v110 = corner_load(vol, x1, y1, z0);
        v101 = corner_load(vol, x1, y0, z1);
        v011 = corner_load(vol, x0, y1, z1);
        v111 = corner_load(vol, x1, y1, z1);
    }

    // Factor the lerp: z first, then y, then x (7 lerps = 14 FMA-class ops).
    float c00 = v000 * gz0 + v001 * fz;
    float c01 = v010 * gz0 + v011 * fz;
    float c10 = v100 * gz0 + v101 * fz;
    float c11 = v110 * gz0 + v111 * fz;
    float c0  = c00 * gy0 + c01 * fy;
    float c1  = c10 * gy0 + c11 * fy;
    return c0 * gx0 + c1 * fx;
}

__global__ __launch_bounds__(256)
void warp3d_kernel(const float* __restrict__ xin,
                   const float* __restrict__ win,
                   float* __restrict__ out) {
    long t = (long)blockIdx.x * blockDim.x + threadIdx.x;
    if (t >= TOTAL_V) return;

    int n  = (int)(t / (HWD / VEC));
    int r4 = (int)(t % (HWD / VEC)) * VEC;   // linear index within map, 4-aligned

    int h   = r4 / WD;
    int rem = r4 % WD;
    int wi  = rem / D;
    int d0  = rem % D;                        // d0..d0+3 same (h, wi) row since D%4==0

    const float* vol = xin + (long)n * HWD;
    const float* fw  = win + (long)n * 3 * HWD;

    float4 f0 = *(const float4*)(fw + 0L * HWD + r4);  // flow along H
    float4 f1 = *(const float4*)(fw + 1L * HWD + r4);  // flow along W
    float4 f2 = *(const float4*)(fw + 2L * HWD + r4);  // flow along D

    float fh = (float)h, fwv = (float)wi;
    float4 o;
    o.x = trilerp(vol, fh + f0.x, fwv + f1.x, (float)(d0 + 0) + f2.x);
    o.y = trilerp(vol, fh + f0.y, fwv + f1.y, (float)(d0 + 1) + f2.y);
    o.z = trilerp(vol, fh + f0.z, fwv + f1.z, (float)(d0 + 2) + f2.z);
    o.w = trilerp(vol, fh + f0.w, fwv + f1.w, (float)(d0 + 3) + f2.w);

    *(float4*)(out + (long)n * HWD + r4) = o;
}

extern "C" void kernel_launch(void* const* d_in, const int* in_sizes, int n_in,
                              void* d_out, int out_size) {
    const float* x = (const float*)d_in[0];
    const float* w = (const float*)d_in[1];
    // x has 3*HWD elements, w has 9*HWD; swap defensively if metadata order differs.
    if (n_in >= 2 && in_sizes[0] > in_sizes[1]) {
        const float* tmp = x; x = w; w = tmp;
    }
    float* out = (float*)d_out;

    int threads = 256;
    long blocks = (TOTAL_V + threads - 1) / threads;
    warp3d_kernel<<<(unsigned)blocks, threads>>>(x, w, out);
}

// round 5
// speedup vs baseline: 1.1004x; 1.1004x over previous
#include <cuda_runtime.h>

// Warp3d: out[n, h, w, d] = trilinear_sample(x[n], grid + flow[n]),
// zeros padding, per the JAX reference.
// Shapes: x (3, H, W, D), w (3, 3, H, W, D), out (3, H, W, D), fp32.
//
// R5 strategy: R2 profile showed L1tex = 74.8% (binding), DRAM = 25%.
// Bottleneck is gather line-wavefronts: 8 scattered LDG.32 per sample.
// Fetch each z-pair (z0, z0+1) via the 8B-aligned float2 at (z0 & ~1):
//   - z0 even (50%): one LDG.64 covers the pair           -> 4 requests
//   - z0 odd:  one extra predicated LDG.64 (half lanes)   -> ~6 effective
// Expected ~25% reduction in gather wavefronts, no scratch memory.

constexpr int H = 160, W = 192, D = 160;
constexpr int WD  = W * D;          // 30720 (even)
constexpr int HWD = H * WD;         // 4915200
constexpr int NMAPS = 3;
constexpr int VEC = 4;              // D % 4 == 0
constexpr long TOTAL_V = (long)NMAPS * HWD / VEC;

__device__ __forceinline__ float corner_load(const float* __restrict__ vol,
                                             int ix, int iy, int iz) {
    bool valid = ((unsigned)ix < (unsigned)H) &
                 ((unsigned)iy < (unsigned)W) &
                 ((unsigned)iz < (unsigned)D);
    int cx = min(max(ix, 0), H - 1);
    int cy = min(max(iy, 0), W - 1);
    int cz = min(max(iz, 0), D - 1);
    float v = __ldg(vol + (long)cx * WD + cy * D + cz);
    return valid ? v : 0.0f;
}

__device__ __forceinline__ float trilerp(const float* __restrict__ vol,
                                         float cx, float cy, float cz) {
    float x0f = floorf(cx), y0f = floorf(cy), z0f = floorf(cz);
    float fx = cx - x0f, fy = cy - y0f, fz = cz - z0f;
    int x0 = (int)x0f, y0 = (int)y0f, z0 = (int)z0f;

    float gx0 = 1.0f - fx, gy0 = 1.0f - fy, gz0 = 1.0f - fz;

    float2 a00, a01, a10, a11;   // values at (z0, z0+1) for the 4 (x,y) rows

    // Fast path: whole 2x2x2 cube strictly in-bounds (>95% of voxels for
    // N(0,1) flow). Aligned-pair fetch:
    //   za = z0 & ~1 is 8B-aligned; for odd z0 a second (predicated) float2
    //   at za+2 supplies z0+1. In the fast path z0 <= D-2, so for odd z0,
    //   za+3 = z0+2 <= D-1: never out of bounds.
    if (((unsigned)x0 < (unsigned)(H - 1)) &
        ((unsigned)y0 < (unsigned)(W - 1)) &
        ((unsigned)z0 < (unsigned)(D - 1))) {
        int za = z0 & ~1;
        bool zodd = (z0 & 1) != 0;
        const float2* p = (const float2*)(vol + (long)x0 * WD + y0 * D + za);

        float2 e00 = __ldg(p);
        float2 e01 = __ldg(p + (D / 2));
        float2 e10 = __ldg(p + (WD / 2));
        float2 e11 = __ldg(p + (WD / 2) + (D / 2));

        float2 h00 = e00, h01 = e01, h10 = e10, h11 = e11;
        if (zodd) {            // predicated: only odd-z0 lanes issue these
            h00 = __ldg(p + 1);
            h01 = __ldg(p + (D / 2) + 1);
            h10 = __ldg(p + (WD / 2) + 1);
            h11 = __ldg(p + (WD / 2) + (D / 2) + 1);
        }
        a00 = zodd ? make_float2(e00.y, h00.x) : e00;
        a01 = zodd ? make_float2(e01.y, h01.x) : e01;
        a10 = zodd ? make_float2(e10.y, h10.x) : e10;
        a11 = zodd ? make_float2(e11.y, h11.x) : e11;
    } else {
        int x1 = x0 + 1, y1 = y0 + 1, z1 = z0 + 1;
        a00.x = corner_load(vol, x0, y0, z0);
        a00.y = corner_load(vol, x0, y0, z1);
        a01.x = corner_load(vol, x0, y1, z0);
        a01.y = corner_load(vol, x0, y1, z1);
        a10.x = corner_load(vol, x1, y0, z0);
        a10.y = corner_load(vol, x1, y0, z1);
        a11.x = corner_load(vol, x1, y1, z0);
        a11.y = corner_load(vol, x1, y1, z1);
    }

    // Factored lerp: z, then y, then x (7 lerps).
    float c00 = a00.x * gz0 + a00.y * fz;
    float c01 = a01.x * gz0 + a01.y * fz;
    float c10 = a10.x * gz0 + a10.y * fz;
    float c11 = a11.x * gz0 + a11.y * fz;
    float c0  = c00 * gy0 + c01 * fy;
    float c1  = c10 * gy0 + c11 * fy;
    return c0 * gx0 + c1 * fx;
}

__global__ __launch_bounds__(256)
void warp3d_kernel(const float* __restrict__ xin,
                   const float* __restrict__ win,
                   float* __restrict__ out) {
    long t = (long)blockIdx.x * blockDim.x + threadIdx.x;
    if (t >= TOTAL_V) return;

    int n  = (int)(t / (HWD / VEC));
    int r4 = (int)(t % (HWD / VEC)) * VEC;   // linear index within map, 4-aligned

    int h   = r4 / WD;
    int rem = r4 % WD;
    int wi  = rem / D;
    int d0  = rem % D;                        // d0..d0+3 same (h, wi) row since D%4==0

    const float* vol = xin + (long)n * HWD;
    const float* fw  = win + (long)n * 3 * HWD;

    float4 f0 = *(const float4*)(fw + 0L * HWD + r4);  // flow along H
    float4 f1 = *(const float4*)(fw + 1L * HWD + r4);  // flow along W
    float4 f2 = *(const float4*)(fw + 2L * HWD + r4);  // flow along D

    float fh = (float)h, fwv = (float)wi;
    float4 o;
    o.x = trilerp(vol, fh + f0.x, fwv + f1.x, (float)(d0 + 0) + f2.x);
    o.y = trilerp(vol, fh + f0.y, fwv + f1.y, (float)(d0 + 1) + f2.y);
    o.z = trilerp(vol, fh + f0.z, fwv + f1.z, (float)(d0 + 2) + f2.z);
    o.w = trilerp(vol, fh + f0.w, fwv + f1.w, (float)(d0 + 3) + f2.w);

    *(float4*)(out + (long)n * HWD + r4) = o;
}

extern "C" void kernel_launch(void* const* d_in, const int* in_sizes, int n_in,
                              void* d_out, int out_size) {
    const float* x = (const float*)d_in[0];
    const float* w = (const float*)d_in[1];
    // x has 3*HWD elements, w has 9*HWD; swap defensively if metadata order differs.
    if (n_in >= 2 && in_sizes[0] > in_sizes[1]) {
        const float* tmp = x; x = w; w = tmp;
    }
    float* out = (float*)d_out;

    int threads = 256;
    long blocks = (TOTAL_V + threads - 1) / threads;
    warp3d_kernel<<<(unsigned)blocks, threads>>>(x, w, out);
}